// round 8
// baseline (speedup 1.0000x reference)
#include <cuda_runtime.h>
#include <cstdint>

#define V 8192
#define NB 64
#define M3 24576
#define STRIDE 8194
#define MT 128
#define NTILE 192            // 24576 / 128 m-tiles
#define KS 16                // split-K factor -> 512 K per unit
#define NUNITS (NTILE * KS)  // 3072
#define GRID 296             // persistent, 2 CTAs/SM
#define KC 32
#define SPU 16               // stages per unit (512/32)
#define NST 3                // cp.async ring depth

#define PC 136               // C tile pitch (floats): conflict-free frag reads
#define PD 72

#define CS_FLOATS (KC * PC)                  // 4352
#define FS_FLOATS (KC * NB)                  // 2048 (packed B-frag layout, no pitch)
#define SB_FLOATS (CS_FLOATS + FS_FLOATS)    // 6400
#define SB_BYTES  (SB_FLOATS * 4)            // 25600
#define DS_OFF    (NST * SB_FLOATS)          // 19200 floats
#define SOUT_OFF  (DS_OFF + 64 * PD)         // 23808
#define SMEM_DYN  ((SOUT_OFF + 192) * 4)     // 96000 B -> 2 CTAs/SM

#define MMA_TF32(d, a0, a1, a2, a3, b0, b1)                                   \
    asm volatile("mma.sync.aligned.m16n8k8.row.col.f32.tf32.tf32.f32 "        \
        "{%0,%1,%2,%3}, {%4,%5,%6,%7}, {%8,%9}, {%0,%1,%2,%3};"               \
        : "+f"((d)[0]), "+f"((d)[1]), "+f"((d)[2]), "+f"((d)[3])              \
        : "r"(a0), "r"(a1), "r"(a2), "r"(a3), "r"(b0), "r"(b1))

#define CP16(dst_u32, src_gl) \
    asm volatile("cp.async.cg.shared.global [%0], [%1], 16;" :: "r"(dst_u32), "l"(src_gl))
#define CP_COMMIT()  asm volatile("cp.async.commit_group;" ::: "memory")
#define CP_WAIT1()   asm volatile("cp.async.wait_group 1;" ::: "memory")

// f packed into per-lane MMA B-fragment layout:
// g_fB[kb8][c][lane][e]  (kb8 = k/8, c = 0..3, lane = qid*4+quad, e = 0..3)
//   k = kb8*8 + quad + (c>=2 ? 4 : 0),  b = qid + 8*((c&1)*4 + e)
__device__ float g_fB[V * NB];   // 2 MB, L2-resident

__device__ __forceinline__ float rn_tf32(float x) {
    return __uint_as_float(__float_as_uint(x) + 0x1000u);
}
__device__ __forceinline__ unsigned fbits_rn(float x) { return __float_as_uint(x) + 0x1000u; }
__device__ __forceinline__ unsigned fbits(float x)    { return __float_as_uint(x); }

// ---------------------------------------------------------------------------
__global__ void prep_kernel(const float* __restrict__ func, float* __restrict__ out) {
    int idx = blockIdx.x * 256 + threadIdx.x;    // < V*NB
    int kb8  = idx >> 9;
    int r    = idx & 511;
    int c    = r >> 7;
    int lane = (r >> 2) & 31;
    int e    = r & 3;
    int quad = lane & 3, qid = lane >> 2;
    int k = kb8 * 8 + quad + ((c >> 1) << 2);
    int b = qid + 8 * ((c & 1) * 4 + e);
    g_fB[idx] = rn_tf32(func[b * STRIDE + k]);
    if (idx < NB) {
        const float QI = 1000000000.0f;
        float a1 = func[idx * STRIDE + V];
        float a2 = func[idx * STRIDE + V + 1];
        out[idx * 3 + 0] = a1 * -QI;
        out[idx * 3 + 1] = (1.0f - (1.0f - a1) * (1.0f - a2)) * -QI;
        out[idx * 3 + 2] = 0.0f;
    }
}

// ---------------------------------------------------------------------------
// Persistent tf32 mma.sync GEMM, 2 CTAs/SM, packed B-fragments.
// ---------------------------------------------------------------------------
__global__ __launch_bounds__(256, 2)
void cooc_mma(const float* __restrict__ cooc,
              const float* __restrict__ arg,
              float* __restrict__ out) {
    extern __shared__ float sm[];
    float* Ds   = sm + DS_OFF;      // 64 x PD (one mt-slab at a time)
    float* sout = sm + SOUT_OFF;

    const int tid  = threadIdx.x;
    const int lane = tid & 31;
    const int wid  = tid >> 5;
    const int mg   = wid & 3;
    const int kg   = wid >> 2;
    const int quad = lane & 3;
    const int qid  = lane >> 2;
    const int bid  = blockIdx.x;

    const int nu    = 1 + (NUNITS - 1 - bid) / GRID;
    const int total = nu * SPU;

    unsigned smem_base;
    asm("{ .reg .u64 t; cvta.to.shared.u64 t, %1; cvt.u32.u64 %0, t; }"
        : "=r"(smem_base) : "l"(sm));

    int crow[4], cc16[4];
    #pragma unroll
    for (int it = 0; it < 4; it++) {
        int flat = it * 256 + tid;
        crow[it] = flat >> 5;
        cc16[it] = flat & 31;
    }

    const char* cooc_g = (const char*)__cvta_generic_to_global(cooc);
    const char* fB_g   = (const char*)__cvta_generic_to_global(g_fB);

    auto issue = [&](int g) {
        int ui = g >> 4, sl = g & 15;
        int u  = bid + ui * GRID;
        int ks = u / NTILE;
        int tile = u - ks * NTILE;
        int m0 = tile * MT;
        int k0 = ks * (V / KS) + sl * KC;
        unsigned buf = smem_base + (unsigned)((g % NST) * SB_BYTES);
        #pragma unroll
        for (int it = 0; it < 4; it++) {
            const char* src = cooc_g + ((size_t)(k0 + crow[it]) * M3 + m0 + cc16[it] * 4) * 4;
            CP16(buf + (unsigned)(crow[it] * PC + cc16[it] * 4) * 4, src);
        }
        // f: contiguous 8KB block, already in B-frag layout
        unsigned fb = buf + CS_FLOATS * 4;
        const char* fsrc = fB_g + ((size_t)(k0 >> 3) * 512) * 4;
        #pragma unroll
        for (int it = 0; it < 2; it++) {
            int flat = it * 256 + tid;
            CP16(fb + (unsigned)flat * 16, fsrc + (size_t)flat * 16);
        }
    };

    float acc[2][8][4];
    #pragma unroll
    for (int mt = 0; mt < 2; mt++)
        #pragma unroll
        for (int nt = 0; nt < 8; nt++)
            #pragma unroll
            for (int r = 0; r < 4; r++) acc[mt][nt][r] = 0.0f;

    float po0 = 0.f, po1 = 0.f, po2 = 0.f;
    const int bb = tid & 63;
    const int mq = tid >> 6;
    const float* argb = arg + bb * STRIDE;

    issue(0); CP_COMMIT();
    issue(1); CP_COMMIT();

    for (int g = 0; g < total; g++) {
        CP_WAIT1();
        __syncthreads();

        if (g + 2 < total) issue(g + 2);
        CP_COMMIT();

        // ---- compute stage g ----
        const float* buf = sm + (g % NST) * SB_FLOATS;
        const float* csA = buf + quad * PC + mg * 32 + qid;
        const float4* Fs4 = (const float4*)(buf + CS_FLOATS);

        #pragma unroll
        for (int kk = 0; kk < 2; kk++) {
            const int kb8l = kg * 2 + kk;           // local 8-k block 0..3
            const float* ca = csA + (kb8l * 8) * PC;

            // B-fragments: 4 conflict-free LDS.128
            float4 B0a = Fs4[kb8l * 128 + lane];          // b0, nt 0..3
            float4 B0b = Fs4[kb8l * 128 + 32 + lane];     // b0, nt 4..7
            float4 B1a = Fs4[kb8l * 128 + 64 + lane];     // b1, nt 0..3
            float4 B1b = Fs4[kb8l * 128 + 96 + lane];     // b1, nt 4..7
            unsigned b0[8], b1[8];
            b0[0] = fbits(B0a.x); b0[1] = fbits(B0a.y); b0[2] = fbits(B0a.z); b0[3] = fbits(B0a.w);
            b0[4] = fbits(B0b.x); b0[5] = fbits(B0b.y); b0[6] = fbits(B0b.z); b0[7] = fbits(B0b.w);
            b1[0] = fbits(B1a.x); b1[1] = fbits(B1a.y); b1[2] = fbits(B1a.z); b1[3] = fbits(B1a.w);
            b1[4] = fbits(B1b.x); b1[5] = fbits(B1b.y); b1[6] = fbits(B1b.z); b1[7] = fbits(B1b.w);

            #pragma unroll
            for (int mt = 0; mt < 2; mt++) {
                unsigned a0 = fbits_rn(ca[mt * 16]);
                unsigned a1 = fbits_rn(ca[mt * 16 + 8]);
                unsigned a2 = fbits_rn(ca[4 * PC + mt * 16]);
                unsigned a3 = fbits_rn(ca[4 * PC + mt * 16 + 8]);
                #pragma unroll
                for (int nt = 0; nt < 8; nt++)
                    MMA_TF32(acc[mt][nt], a0, a1, a2, a3, b0[nt], b1[nt]);
            }
        }

        // ---- unit boundary: two-pass fold + reduce ----
        if ((g & (SPU - 1)) == SPU - 1) {
            int u  = bid + (g >> 4) * GRID;
            int ks = u / NTILE;
            int m0 = (u - ks * NTILE) * MT;

            #pragma unroll
            for (int p = 0; p < 2; p++) {
                __syncthreads();
                if (kg == 0) {
                    int cr = mg * 16 + qid;
                    #pragma unroll
                    for (int nt = 0; nt < 8; nt++) {
                        int bc = nt * 8 + 2 * quad;
                        Ds[cr * PD + bc]           = acc[p][nt][0];
                        Ds[cr * PD + bc + 1]       = acc[p][nt][1];
                        Ds[(cr + 8) * PD + bc]     = acc[p][nt][2];
                        Ds[(cr + 8) * PD + bc + 1] = acc[p][nt][3];
                    }
                }
                __syncthreads();
                if (kg == 1) {
                    int cr = mg * 16 + qid;
                    #pragma unroll
                    for (int nt = 0; nt < 8; nt++) {
                        int bc = nt * 8 + 2 * quad;
                        Ds[cr * PD + bc]           += acc[p][nt][0];
                        Ds[cr * PD + bc + 1]       += acc[p][nt][1];
                        Ds[(cr + 8) * PD + bc]     += acc[p][nt][2];
                        Ds[(cr + 8) * PD + bc + 1] += acc[p][nt][3];
                    }
                }
                __syncthreads();
                // reduce this slab: thread (bb, mq) over 16 rows
                #pragma unroll 4
                for (int mm = 0; mm < 16; mm++) {
                    int m = m0 + mq * 32 + p * 16 + mm;
                    unsigned j = (unsigned)m / 3u;
                    int k = m - 3 * (int)j;
                    float t = Ds[(mq * 16 + mm) * PD + bb] * __ldg(argb + j);
                    if (k == 0) po0 += t;
                    else if (k == 1) po1 += t;
                    else po2 += t;
                }
            }
            __syncthreads();

            #pragma unroll
            for (int mt = 0; mt < 2; mt++)
                #pragma unroll
                for (int nt = 0; nt < 8; nt++)
                    #pragma unroll
                    for (int r = 0; r < 4; r++) acc[mt][nt][r] = 0.0f;
        }
    }

    // ---- final flush ----
    if (tid < 192) sout[tid] = 0.0f;
    __syncthreads();
    atomicAdd(&sout[bb * 3 + 0], po0);
    atomicAdd(&sout[bb * 3 + 1], po1);
    atomicAdd(&sout[bb * 3 + 2], po2);
    __syncthreads();
    if (tid < 192) atomicAdd(&out[tid], sout[tid]);
}

// ---------------------------------------------------------------------------
extern "C" void kernel_launch(void* const* d_in, const int* in_sizes, int n_in,
                              void* d_out, int out_size) {
    const float* func = (const float*)d_in[0];
    const float* arg  = (const float*)d_in[1];
    const float* cooc = (const float*)d_in[2];
    float* out = (float*)d_out;

    cudaFuncSetAttribute(cooc_mma, cudaFuncAttributeMaxDynamicSharedMemorySize, SMEM_DYN);

    prep_kernel<<<(V * NB) / 256, 256>>>(func, out);
    cooc_mma<<<GRID, 256, SMEM_DYN>>>(cooc, arg, out);
}

// round 9
// speedup vs baseline: 1.0270x; 1.0270x over previous
#include <cuda_runtime.h>
#include <cstdint>

#define V 8192
#define NB 64
#define M3 24576
#define STRIDE 8194
#define MT 128
#define NTILE 192            // 24576 / 128 m-tiles
#define KS 16                // split-K factor -> 512 K per unit
#define NUNITS (NTILE * KS)  // 3072
#define GRID 296             // persistent, 2 CTAs/SM
#define KC 32
#define SPU 16               // stages per unit (512/32)
#define NST 3                // cp.async ring depth

#define PC 136               // C tile pitch (floats): conflict-free frag reads
#define PF 72
#define PD 72

#define CS_FLOATS (KC * PC)                  // 4352
#define FS_FLOATS (KC * PF)                  // 2304
#define SB_FLOATS (CS_FLOATS + FS_FLOATS)    // 6656
#define SB_BYTES  (SB_FLOATS * 4)
#define DS_OFF    (NST * SB_FLOATS)          // 19968 floats
#define SOUT_OFF  (DS_OFF + 64 * PD)
#define SMEM_DYN  ((SOUT_OFF + 192) * 4)     // 99072 B -> 2 CTAs/SM

#define MMA_TF32(d, a0, a1, a2, a3, b0, b1)                                   \
    asm volatile("mma.sync.aligned.m16n8k8.row.col.f32.tf32.tf32.f32 "        \
        "{%0,%1,%2,%3}, {%4,%5,%6,%7}, {%8,%9}, {%0,%1,%2,%3};"               \
        : "+f"((d)[0]), "+f"((d)[1]), "+f"((d)[2]), "+f"((d)[3])              \
        : "r"(a0), "r"(a1), "r"(a2), "r"(a3), "r"(b0), "r"(b1))

#define CP16(dst_u32, src_gl) \
    asm volatile("cp.async.cg.shared.global [%0], [%1], 16;" :: "r"(dst_u32), "l"(src_gl))
#define CP_COMMIT()  asm volatile("cp.async.commit_group;" ::: "memory")
#define CP_WAIT1()   asm volatile("cp.async.wait_group 1;" ::: "memory")

__device__ float g_fT[V * NB];   // 2 MB, L2-resident: f transposed [i][b], tf32-rounded

__device__ __forceinline__ float rn_tf32(float x) {
    return __uint_as_float(__float_as_uint(x) + 0x1000u);
}
__device__ __forceinline__ unsigned fbits(float x) { return __float_as_uint(x); }

// ---------------------------------------------------------------------------
__global__ void prep_kernel(const float* __restrict__ func, float* __restrict__ out) {
    int idx = blockIdx.x * 256 + threadIdx.x;    // < V*NB
    int i = idx >> 6;
    int b = idx & 63;
    g_fT[idx] = rn_tf32(func[b * STRIDE + i]);   // f rounded (positive -> bias matters)
    if (idx < NB) {
        const float QI = 1000000000.0f;
        float a1 = func[idx * STRIDE + V];
        float a2 = func[idx * STRIDE + V + 1];
        out[idx * 3 + 0] = a1 * -QI;
        out[idx * 3 + 1] = (1.0f - (1.0f - a1) * (1.0f - a2)) * -QI;
        out[idx * 3 + 2] = 0.0f;
    }
}

// ---------------------------------------------------------------------------
// Persistent tf32 mma.sync GEMM, 2 CTAs/SM, units = 128m x 512K.
// C operand deliberately NOT rounded (truncation unbiased: C symmetric).
// ---------------------------------------------------------------------------
__global__ __launch_bounds__(256, 2)
void cooc_mma(const float* __restrict__ cooc,
              const float* __restrict__ arg,
              float* __restrict__ out) {
    extern __shared__ float sm[];
    float* Ds   = sm + DS_OFF;      // 64 x PD (one mt-slab at a time)
    float* sout = sm + SOUT_OFF;

    const int tid  = threadIdx.x;
    const int lane = tid & 31;
    const int wid  = tid >> 5;
    const int mg   = wid & 3;
    const int kg   = wid >> 2;
    const int quad = lane & 3;
    const int qid  = lane >> 2;
    const int bid  = blockIdx.x;

    const int nu    = 1 + (NUNITS - 1 - bid) / GRID;
    const int total = nu * SPU;

    unsigned smem_base;
    asm("{ .reg .u64 t; cvta.to.shared.u64 t, %1; cvt.u32.u64 %0, t; }"
        : "=r"(smem_base) : "l"(sm));

    int crow[4], cc16[4];
    #pragma unroll
    for (int it = 0; it < 4; it++) {
        int flat = it * 256 + tid;
        crow[it] = flat >> 5;
        cc16[it] = flat & 31;
    }
    int frow[2], fc16[2];
    #pragma unroll
    for (int it = 0; it < 2; it++) {
        int flat = it * 256 + tid;
        frow[it] = flat >> 4;
        fc16[it] = flat & 15;
    }

    const char* cooc_g = (const char*)__cvta_generic_to_global(cooc);
    const char* fT_g   = (const char*)__cvta_generic_to_global(g_fT);

    // -------- incremental issue-stream state (avoids per-stage div/mod) ----
    int u_i  = bid;
    int sl_i = 0;
    int m0_i, k0_i;
    {
        int ks = u_i / NTILE;
        m0_i = (u_i - ks * NTILE) * MT;
        k0_i = ks * (V / KS);
    }
    int slot_i = 0;   // ring slot for next issue

    auto issue = [&]() {
        unsigned buf = smem_base + (unsigned)(slot_i * SB_BYTES);
        #pragma unroll
        for (int it = 0; it < 4; it++) {
            const char* src = cooc_g + ((size_t)(k0_i + crow[it]) * M3 + m0_i + cc16[it] * 4) * 4;
            CP16(buf + (unsigned)(crow[it] * PC + cc16[it] * 4) * 4, src);
        }
        unsigned fb = buf + CS_FLOATS * 4;
        #pragma unroll
        for (int it = 0; it < 2; it++) {
            const char* src = fT_g + ((size_t)(k0_i + frow[it]) * NB + fc16[it] * 4) * 4;
            CP16(fb + (unsigned)(frow[it] * PF + fc16[it] * 4) * 4, src);
        }
    };
    auto adv = [&]() {
        slot_i = (slot_i == NST - 1) ? 0 : slot_i + 1;
        if (++sl_i == SPU) {
            sl_i = 0;
            u_i += GRID;
            if (u_i < NUNITS) {
                int ks = u_i / NTILE;
                m0_i = (u_i - ks * NTILE) * MT;
                k0_i = ks * (V / KS);
            }
        } else {
            k0_i += KC;
        }
    };

    float acc[2][8][4];
    #pragma unroll
    for (int mt = 0; mt < 2; mt++)
        #pragma unroll
        for (int nt = 0; nt < 8; nt++)
            #pragma unroll
            for (int r = 0; r < 4; r++) acc[mt][nt][r] = 0.0f;

    float po0 = 0.f, po1 = 0.f, po2 = 0.f;
    const int bb = tid & 63;
    const int mq = tid >> 6;
    const float* argb = arg + bb * STRIDE;

    // compute-side unit state
    int u_c  = bid;
    int m0_c;
    {
        int ks = u_c / NTILE;
        m0_c = (u_c - ks * NTILE) * MT;
    }

    issue(); CP_COMMIT(); adv();
    issue(); CP_COMMIT(); adv();

    int slot_c = 0;   // ring slot for compute

    for (int g = 0; g < total; g++) {
        CP_WAIT1();
        __syncthreads();

        if (g + 2 < total) issue();
        CP_COMMIT();
        adv();

        // ---- compute stage g ----
        const float* buf = sm + slot_c * SB_FLOATS;
        slot_c = (slot_c == NST - 1) ? 0 : slot_c + 1;
        const float* csA = buf + quad * PC + mg * 32 + qid;
        const float* fsB = buf + CS_FLOATS + quad * PF + qid;

        #pragma unroll
        for (int kk = 0; kk < 2; kk++) {
            const int kb = kg * 16 + kk * 8;
            const float* ca = csA + kb * PC;
            const float* fb = fsB + kb * PF;
            unsigned b0[8], b1[8];
            #pragma unroll
            for (int nt = 0; nt < 8; nt++) {
                b0[nt] = fbits(fb[nt * 8]);
                b1[nt] = fbits(fb[4 * PF + nt * 8]);
            }
            #pragma unroll
            for (int mt = 0; mt < 2; mt++) {
                unsigned a0 = fbits(ca[mt * 16]);           // raw: tf32 truncation unbiased
                unsigned a1 = fbits(ca[mt * 16 + 8]);
                unsigned a2 = fbits(ca[4 * PC + mt * 16]);
                unsigned a3 = fbits(ca[4 * PC + mt * 16 + 8]);
                #pragma unroll
                for (int nt = 0; nt < 8; nt++)
                    MMA_TF32(acc[mt][nt], a0, a1, a2, a3, b0[nt], b1[nt]);
            }
        }

        // ---- unit boundary: two-pass fold + reduce ----
        if ((g & (SPU - 1)) == SPU - 1) {
            #pragma unroll
            for (int p = 0; p < 2; p++) {
                __syncthreads();
                if (kg == 0) {
                    int cr = mg * 16 + qid;
                    #pragma unroll
                    for (int nt = 0; nt < 8; nt++) {
                        int bc = nt * 8 + 2 * quad;
                        Ds[cr * PD + bc]           = acc[p][nt][0];
                        Ds[cr * PD + bc + 1]       = acc[p][nt][1];
                        Ds[(cr + 8) * PD + bc]     = acc[p][nt][2];
                        Ds[(cr + 8) * PD + bc + 1] = acc[p][nt][3];
                    }
                }
                __syncthreads();
                if (kg == 1) {
                    int cr = mg * 16 + qid;
                    #pragma unroll
                    for (int nt = 0; nt < 8; nt++) {
                        int bc = nt * 8 + 2 * quad;
                        Ds[cr * PD + bc]           += acc[p][nt][0];
                        Ds[cr * PD + bc + 1]       += acc[p][nt][1];
                        Ds[(cr + 8) * PD + bc]     += acc[p][nt][2];
                        Ds[(cr + 8) * PD + bc + 1] += acc[p][nt][3];
                    }
                }
                __syncthreads();
                // reduce this slab: thread (bb, mq) over 16 rows
                #pragma unroll 4
                for (int mm = 0; mm < 16; mm++) {
                    int m = m0_c + mq * 32 + p * 16 + mm;
                    unsigned j = (unsigned)m / 3u;
                    int k = m - 3 * (int)j;
                    float t = Ds[(mq * 16 + mm) * PD + bb] * __ldg(argb + j);
                    if (k == 0) po0 += t;
                    else if (k == 1) po1 += t;
                    else po2 += t;
                }
            }
            __syncthreads();

            #pragma unroll
            for (int mt = 0; mt < 2; mt++)
                #pragma unroll
                for (int nt = 0; nt < 8; nt++)
                    #pragma unroll
                    for (int r = 0; r < 4; r++) acc[mt][nt][r] = 0.0f;

            // advance compute-side unit state
            u_c += GRID;
            if (u_c < NUNITS) {
                int ks = u_c / NTILE;
                m0_c = (u_c - ks * NTILE) * MT;
            }
        }
    }

    // ---- final flush ----
    if (tid < 192) sout[tid] = 0.0f;
    __syncthreads();
    atomicAdd(&sout[bb * 3 + 0], po0);
    atomicAdd(&sout[bb * 3 + 1], po1);
    atomicAdd(&sout[bb * 3 + 2], po2);
    __syncthreads();
    if (tid < 192) atomicAdd(&out[tid], sout[tid]);
}

// ---------------------------------------------------------------------------
extern "C" void kernel_launch(void* const* d_in, const int* in_sizes, int n_in,
                              void* d_out, int out_size) {
    const float* func = (const float*)d_in[0];
    const float* arg  = (const float*)d_in[1];
    const float* cooc = (const float*)d_in[2];
    float* out = (float*)d_out;

    cudaFuncSetAttribute(cooc_mma, cudaFuncAttributeMaxDynamicSharedMemorySize, SMEM_DYN);

    prep_kernel<<<(V * NB) / 256, 256>>>(func, out);
    cooc_mma<<<GRID, 256, SMEM_DYN>>>(cooc, arg, out);
}

// round 10
// speedup vs baseline: 1.1712x; 1.1404x over previous
#include <cuda_runtime.h>
#include <cstdint>

#define V 8192
#define NB 64
#define M3 24576
#define STRIDE 8194
#define MT 128
#define NTILE 192            // 24576 / 128 m-tiles
#define KS 16                // split-K factor -> 512 K per unit
#define NUNITS (NTILE * KS)  // 3072
#define GRID 296             // persistent, 2 CTAs/SM
#define KC 32
#define SPU 16               // stages per unit (512/32)
#define NST 3                // cp.async ring depth

#define PC 132               // C tile pitch (floats): 2-row stride 264%32=8 -> conflict-free
#define PFW 72               // f pair-tile pitch (words)
#define PD 72

#define CS_FLOATS (KC * PC)                  // 4224
#define FS_WORDS  (16 * PFW)                 // 1152 (16 k2-rows)
#define SB_FLOATS (CS_FLOATS + FS_WORDS)     // 5376
#define SB_BYTES  (SB_FLOATS * 4)            // 21504
#define DS_OFF    (NST * SB_FLOATS)          // 16128
#define SOUT_OFF  (DS_OFF + 64 * PD)         // 20736
#define SMEM_DYN  ((SOUT_OFF + 192) * 4)     // 83712 B -> 2 CTAs/SM

#define MMA_BF16(d, a0, a1, a2, a3, b0, b1)                                   \
    asm volatile("mma.sync.aligned.m16n8k16.row.col.f32.bf16.bf16.f32 "       \
        "{%0,%1,%2,%3}, {%4,%5,%6,%7}, {%8,%9}, {%0,%1,%2,%3};"               \
        : "+f"((d)[0]), "+f"((d)[1]), "+f"((d)[2]), "+f"((d)[3])              \
        : "r"(a0), "r"(a1), "r"(a2), "r"(a3), "r"(b0), "r"(b1))

#define CP16(dst_u32, src_gl) \
    asm volatile("cp.async.cg.shared.global [%0], [%1], 16;" :: "r"(dst_u32), "l"(src_gl))
#define CP_COMMIT()  asm volatile("cp.async.commit_group;" ::: "memory")
#define CP_WAIT1()   asm volatile("cp.async.wait_group 1;" ::: "memory")

// f packed as bf16 k-pairs: g_fP[i2*64 + b] = {lo: f[b][2*i2], hi: f[b][2*i2+1]}
__device__ unsigned g_fP[(V / 2) * NB];   // 1 MB, L2-resident

__device__ __forceinline__ unsigned pack_bf16(float lo, float hi) {
    unsigned r;
    asm("cvt.rn.bf16x2.f32 %0, %1, %2;" : "=r"(r) : "f"(hi), "f"(lo));
    return r;
}

// ---------------------------------------------------------------------------
__global__ void prep_kernel(const float* __restrict__ func, float* __restrict__ out) {
    int idx = blockIdx.x * 256 + threadIdx.x;    // < (V/2)*NB = 262144
    int i2 = idx >> 6;
    int b  = idx & 63;
    float lo = func[b * STRIDE + 2 * i2];
    float hi = func[b * STRIDE + 2 * i2 + 1];
    g_fP[idx] = pack_bf16(lo, hi);
    if (idx < NB) {
        const float QI = 1000000000.0f;
        float a1 = func[idx * STRIDE + V];
        float a2 = func[idx * STRIDE + V + 1];
        out[idx * 3 + 0] = a1 * -QI;
        out[idx * 3 + 1] = (1.0f - (1.0f - a1) * (1.0f - a2)) * -QI;
        out[idx * 3 + 2] = 0.0f;
    }
}

// ---------------------------------------------------------------------------
// Persistent bf16 mma.sync (m16n8k16) GEMM, 2 CTAs/SM, units = 128m x 512K.
// C streamed fp32 via cp.async, converted to bf16 in-register (RN).
// ---------------------------------------------------------------------------
__global__ __launch_bounds__(256, 2)
void cooc_mma(const float* __restrict__ cooc,
              const float* __restrict__ arg,
              float* __restrict__ out) {
    extern __shared__ float sm[];
    float* Ds   = sm + DS_OFF;      // 64 x PD (one mt-slab at a time)
    float* sout = sm + SOUT_OFF;

    const int tid  = threadIdx.x;
    const int lane = tid & 31;
    const int wid  = tid >> 5;
    const int mg   = wid & 3;
    const int kg   = wid >> 2;
    const int quad = lane & 3;
    const int qid  = lane >> 2;
    const int bid  = blockIdx.x;

    const int nu    = 1 + (NUNITS - 1 - bid) / GRID;
    const int total = nu * SPU;

    unsigned smem_base;
    asm("{ .reg .u64 t; cvta.to.shared.u64 t, %1; cvt.u32.u64 %0, t; }"
        : "=r"(smem_base) : "l"(sm));

    int crow[4], cc16[4];
    #pragma unroll
    for (int it = 0; it < 4; it++) {
        int flat = it * 256 + tid;
        crow[it] = flat >> 5;
        cc16[it] = flat & 31;
    }
    const int f_row = tid >> 4;     // 0..15 (k2 rows)
    const int f_c16 = tid & 15;

    const char* cooc_g = (const char*)__cvta_generic_to_global(cooc);
    const char* fP_g   = (const char*)__cvta_generic_to_global(g_fP);

    // -------- incremental issue-stream state ----
    int u_i  = bid;
    int sl_i = 0;
    int m0_i, k0_i;
    {
        int ks = u_i / NTILE;
        m0_i = (u_i - ks * NTILE) * MT;
        k0_i = ks * (V / KS);
    }
    int slot_i = 0;

    auto issue = [&]() {
        unsigned buf = smem_base + (unsigned)(slot_i * SB_BYTES);
        #pragma unroll
        for (int it = 0; it < 4; it++) {
            const char* src = cooc_g + ((size_t)(k0_i + crow[it]) * M3 + m0_i + cc16[it] * 4) * 4;
            CP16(buf + (unsigned)(crow[it] * PC + cc16[it] * 4) * 4, src);
        }
        // f: 16 k2-rows x 256B, contiguous 4KB in global
        unsigned fb = buf + CS_FLOATS * 4;
        const char* fsrc = fP_g + ((size_t)((k0_i >> 1) + f_row) * 64 + f_c16 * 4) * 4;
        CP16(fb + (unsigned)(f_row * PFW + f_c16 * 4) * 4, fsrc);
    };
    auto adv = [&]() {
        slot_i = (slot_i == NST - 1) ? 0 : slot_i + 1;
        if (++sl_i == SPU) {
            sl_i = 0;
            u_i += GRID;
            if (u_i < NUNITS) {
                int ks = u_i / NTILE;
                m0_i = (u_i - ks * NTILE) * MT;
                k0_i = ks * (V / KS);
            }
        } else {
            k0_i += KC;
        }
    };

    float acc[2][8][4];
    #pragma unroll
    for (int mt = 0; mt < 2; mt++)
        #pragma unroll
        for (int nt = 0; nt < 8; nt++)
            #pragma unroll
            for (int r = 0; r < 4; r++) acc[mt][nt][r] = 0.0f;

    float po0 = 0.f, po1 = 0.f, po2 = 0.f;
    const int bb = tid & 63;
    const int mq = tid >> 6;
    const float* argb = arg + bb * STRIDE;

    int u_c  = bid;
    int m0_c;
    {
        int ks = u_c / NTILE;
        m0_c = (u_c - ks * NTILE) * MT;
    }

    issue(); CP_COMMIT(); adv();
    issue(); CP_COMMIT(); adv();

    int slot_c = 0;

    for (int g = 0; g < total; g++) {
        CP_WAIT1();
        __syncthreads();

        if (g + 2 < total) issue();
        CP_COMMIT();
        adv();

        // ---- compute stage g ----
        const float* buf = sm + slot_c * SB_FLOATS;
        slot_c = (slot_c == NST - 1) ? 0 : slot_c + 1;

        // A (C-matrix) base: rows kg*16 + 2*quad + {0,1,8,9}, cols mg*32 + qid
        const float* ca = buf + (kg * 16 + 2 * quad) * PC + mg * 32 + qid;
        // B (f) base: k2-rows kg*8 + quad + {0,4}, col nt*8 + qid
        const unsigned* fb = (const unsigned*)(buf + CS_FLOATS) + (kg * 8 + quad) * PFW + qid;

        unsigned b0[8], b1[8];
        #pragma unroll
        for (int nt = 0; nt < 8; nt++) {
            b0[nt] = fb[nt * 8];
            b1[nt] = fb[4 * PFW + nt * 8];
        }

        #pragma unroll
        for (int mt = 0; mt < 2; mt++) {
            const float* cm = ca + mt * 16;
            unsigned a0 = pack_bf16(cm[0],          cm[PC]);
            unsigned a1 = pack_bf16(cm[8],          cm[PC + 8]);
            unsigned a2 = pack_bf16(cm[8 * PC],     cm[9 * PC]);
            unsigned a3 = pack_bf16(cm[8 * PC + 8], cm[9 * PC + 8]);
            #pragma unroll
            for (int nt = 0; nt < 8; nt++)
                MMA_BF16(acc[mt][nt], a0, a1, a2, a3, b0[nt], b1[nt]);
        }

        // ---- unit boundary: two-pass fold + reduce ----
        if ((g & (SPU - 1)) == SPU - 1) {
            #pragma unroll
            for (int p = 0; p < 2; p++) {
                __syncthreads();
                if (kg == 0) {
                    int cr = mg * 16 + qid;
                    #pragma unroll
                    for (int nt = 0; nt < 8; nt++) {
                        int bc = nt * 8 + 2 * quad;
                        Ds[cr * PD + bc]           = acc[p][nt][0];
                        Ds[cr * PD + bc + 1]       = acc[p][nt][1];
                        Ds[(cr + 8) * PD + bc]     = acc[p][nt][2];
                        Ds[(cr + 8) * PD + bc + 1] = acc[p][nt][3];
                    }
                }
                __syncthreads();
                if (kg == 1) {
                    int cr = mg * 16 + qid;
                    #pragma unroll
                    for (int nt = 0; nt < 8; nt++) {
                        int bc = nt * 8 + 2 * quad;
                        Ds[cr * PD + bc]           += acc[p][nt][0];
                        Ds[cr * PD + bc + 1]       += acc[p][nt][1];
                        Ds[(cr + 8) * PD + bc]     += acc[p][nt][2];
                        Ds[(cr + 8) * PD + bc + 1] += acc[p][nt][3];
                    }
                }
                __syncthreads();
                #pragma unroll 4
                for (int mm = 0; mm < 16; mm++) {
                    int m = m0_c + mq * 32 + p * 16 + mm;
                    unsigned j = (unsigned)m / 3u;
                    int k = m - 3 * (int)j;
                    float t = Ds[(mq * 16 + mm) * PD + bb] * __ldg(argb + j);
                    if (k == 0) po0 += t;
                    else if (k == 1) po1 += t;
                    else po2 += t;
                }
            }
            __syncthreads();

            #pragma unroll
            for (int mt = 0; mt < 2; mt++)
                #pragma unroll
                for (int nt = 0; nt < 8; nt++)
                    #pragma unroll
                    for (int r = 0; r < 4; r++) acc[mt][nt][r] = 0.0f;

            u_c += GRID;
            if (u_c < NUNITS) {
                int ks = u_c / NTILE;
                m0_c = (u_c - ks * NTILE) * MT;
            }
        }
    }

    // ---- final flush ----
    if (tid < 192) sout[tid] = 0.0f;
    __syncthreads();
    atomicAdd(&sout[bb * 3 + 0], po0);
    atomicAdd(&sout[bb * 3 + 1], po1);
    atomicAdd(&sout[bb * 3 + 2], po2);
    __syncthreads();
    if (tid < 192) atomicAdd(&out[tid], sout[tid]);
}

// ---------------------------------------------------------------------------
extern "C" void kernel_launch(void* const* d_in, const int* in_sizes, int n_in,
                              void* d_out, int out_size) {
    const float* func = (const float*)d_in[0];
    const float* arg  = (const float*)d_in[1];
    const float* cooc = (const float*)d_in[2];
    float* out = (float*)d_out;

    cudaFuncSetAttribute(cooc_mma, cudaFuncAttributeMaxDynamicSharedMemorySize, SMEM_DYN);

    prep_kernel<<<((V / 2) * NB) / 256, 256>>>(func, out);
    cooc_mma<<<GRID, 256, SMEM_DYN>>>(cooc, arg, out);
}